// round 2
// baseline (speedup 1.0000x reference)
#include <cuda_runtime.h>
#include <math.h>

// SurfNetwork fused kernel, fp32 with packed f32x2 FFMA2 (Blackwell).
// Inputs (metadata order): x(int32 B*N*L), d(f32 B*16), gridWeight(f32 4M*4),
// W0(34*64), b0(64), W1(64*64), b1(64), W2(64*3), b2(3).
// Output: [sigma (B*N)] ++ [colorSum (B*3)], float32.

#define BN   128   // N samples per batch row
#define LVL  6
#define DIRD 16
#define HID  64
#define IN0  34    // DIRD + LVL*3

typedef unsigned long long u64;

__device__ __forceinline__ u64 pk2(float v) {
    u64 r; asm("mov.b64 %0,{%1,%2};" : "=l"(r) : "f"(v), "f"(v)); return r;
}
__device__ __forceinline__ u64 ffma2(u64 a, u64 b, u64 c) {
    u64 d; asm("fma.rn.f32x2 %0,%1,%2,%3;" : "=l"(d) : "l"(a), "l"(b), "l"(c)); return d;
}
__device__ __forceinline__ void upk2(u64 a, float& lo, float& hi) {
    asm("mov.b64 {%0,%1},%2;" : "=f"(lo), "=f"(hi) : "l"(a));
}

__global__ __launch_bounds__(128)
void surf_kernel(const int* __restrict__ x,
                 const float* __restrict__ d,
                 const float4* __restrict__ gw,
                 const float* __restrict__ W0, const float* __restrict__ b0,
                 const float* __restrict__ W1, const float* __restrict__ b1,
                 const float* __restrict__ W2, const float* __restrict__ b2,
                 float* __restrict__ outSigma, float* __restrict__ outColor,
                 int B)
{
    __shared__ __align__(16) float sW0[IN0 * HID];
    __shared__ __align__(16) float sW1[HID * HID];
    __shared__ __align__(16) float sW2[HID * 3];
    __shared__ __align__(16) float sB0[HID];
    __shared__ __align__(16) float sB1[HID];
    __shared__ __align__(16) float sBase[HID];
    __shared__ float sB2[4];
    __shared__ float sSig[BN];
    __shared__ float sMaxW[4];
    __shared__ float sColW[4][3];

    const int tid  = threadIdx.x;
    const int lane = tid & 31;
    const int warp = tid >> 5;

    // Stage weights in SMEM once per block.
    for (int i = tid; i < IN0 * HID; i += 128) sW0[i] = W0[i];
    for (int i = tid; i < HID * HID; i += 128) sW1[i] = W1[i];
    for (int i = tid; i < HID * 3;   i += 128) sW2[i] = W2[i];
    if (tid < HID) { sB0[tid] = b0[tid]; sB1[tid] = b1[tid]; }
    if (tid < 3) sB2[tid] = b2[tid];
    __syncthreads();

    for (int bb = blockIdx.x; bb < B; bb += gridDim.x) {
        // Per-batch base = b0 + d[bb] . W0[:16,:]  (shared by all 128 samples)
        if (tid < HID) {
            float acc = sB0[tid];
            const float* dd = d + (size_t)bb * DIRD;
            #pragma unroll
            for (int i = 0; i < DIRD; i++) acc = fmaf(__ldg(dd + i), sW0[i * HID + tid], acc);
            sBase[tid] = acc;
        }

        // Gather 6 grid-feature rows for this sample.
        const int* xp = x + ((size_t)bb * BN + tid) * LVL;
        float geo[LVL * 3];
        float sig0 = 1.0f;
        #pragma unroll
        for (int l = 0; l < LVL; l++) {
            int idx = __ldg(xp + l);
            float4 f = __ldg(gw + idx);
            float s = fminf(fmaxf(f.x, 0.0f), 1.0f);
            sig0 *= s;
            geo[l * 3 + 0] = f.y;
            geo[l * 3 + 1] = f.z;
            geo[l * 3 + 2] = f.w;
        }
        sig0 += 1e-4f;
        sSig[tid] = sig0;

        // Block max over the 128 samples of this batch row.
        float m = sig0;
        #pragma unroll
        for (int o = 16; o; o >>= 1) m = fmaxf(m, __shfl_xor_sync(0xffffffffu, m, o));
        if (lane == 0) sMaxW[warp] = m;
        __syncthreads();
        m = fmaxf(fmaxf(sMaxW[0], sMaxW[1]), fmaxf(sMaxW[2], sMaxW[3]));

        float sigma = sig0 / m;
        outSigma[(size_t)bb * BN + tid] = sigma;
        float tb = (tid == 0) ? 1.0f : (1.0f - sSig[tid - 1] / m);
        float cw = tb * sigma;

        // ---------------- MLP (packed f32x2) ----------------
        u64 a[HID / 2];
        // Layer 0: acc = base + geo . W0[16:34,:]
        {
            const u64* bp = (const u64*)sBase;
            #pragma unroll
            for (int j = 0; j < HID / 2; j++) a[j] = bp[j];
            #pragma unroll
            for (int i = 0; i < LVL * 3; i++) {
                u64 xx = pk2(geo[i]);
                const ulonglong2* w = (const ulonglong2*)(sW0 + (DIRD + i) * HID);
                #pragma unroll
                for (int j = 0; j < HID / 4; j++) {
                    ulonglong2 ww = w[j];
                    a[2 * j]     = ffma2(xx, ww.x, a[2 * j]);
                    a[2 * j + 1] = ffma2(xx, ww.y, a[2 * j + 1]);
                }
            }
        }
        float h[HID];
        #pragma unroll
        for (int j = 0; j < HID / 2; j++) {
            float lo, hi; upk2(a[j], lo, hi);
            h[2 * j]     = fmaxf(lo, 0.0f);
            h[2 * j + 1] = fmaxf(hi, 0.0f);
        }
        // Layer 1: acc = b1 + h . W1
        {
            const u64* bp = (const u64*)sB1;
            #pragma unroll
            for (int j = 0; j < HID / 2; j++) a[j] = bp[j];
            #pragma unroll 8
            for (int i = 0; i < HID; i++) {
                u64 xx = pk2(h[i]);
                const ulonglong2* w = (const ulonglong2*)(sW1 + i * HID);
                #pragma unroll
                for (int j = 0; j < HID / 4; j++) {
                    ulonglong2 ww = w[j];
                    a[2 * j]     = ffma2(xx, ww.x, a[2 * j]);
                    a[2 * j + 1] = ffma2(xx, ww.y, a[2 * j + 1]);
                }
            }
        }
        #pragma unroll
        for (int j = 0; j < HID / 2; j++) {
            float lo, hi; upk2(a[j], lo, hi);
            h[2 * j]     = fmaxf(lo, 0.0f);
            h[2 * j + 1] = fmaxf(hi, 0.0f);
        }
        // Layer 2: logits (3) + sigmoid
        float l0 = sB2[0], l1 = sB2[1], l2 = sB2[2];
        #pragma unroll 16
        for (int i = 0; i < HID; i++) {
            float hv = h[i];
            l0 = fmaf(hv, sW2[i * 3 + 0], l0);
            l1 = fmaf(hv, sW2[i * 3 + 1], l1);
            l2 = fmaf(hv, sW2[i * 3 + 2], l2);
        }
        float c0 = 1.0f / (1.0f + expf(-l0));
        float c1 = 1.0f / (1.0f + expf(-l1));
        float c2 = 1.0f / (1.0f + expf(-l2));

        // Weighted color reduction over the 128 samples.
        float r = cw * c0, g = cw * c1, bcl = cw * c2;
        #pragma unroll
        for (int o = 16; o; o >>= 1) {
            r   += __shfl_xor_sync(0xffffffffu, r, o);
            g   += __shfl_xor_sync(0xffffffffu, g, o);
            bcl += __shfl_xor_sync(0xffffffffu, bcl, o);
        }
        if (lane == 0) { sColW[warp][0] = r; sColW[warp][1] = g; sColW[warp][2] = bcl; }
        __syncthreads();
        if (tid < 3) {
            outColor[(size_t)bb * 3 + tid] =
                sColW[0][tid] + sColW[1][tid] + sColW[2][tid] + sColW[3][tid];
        }
        __syncthreads();  // protect sSig/sBase/sMaxW/sColW before next iteration
    }
}

extern "C" void kernel_launch(void* const* d_in, const int* in_sizes, int n_in,
                              void* d_out, int out_size)
{
    const int*   x  = (const int*)d_in[0];
    const float* dv = (const float*)d_in[1];
    const float4* gw = (const float4*)d_in[2];
    const float* W0 = (const float*)d_in[3];
    const float* b0 = (const float*)d_in[4];
    const float* W1 = (const float*)d_in[5];
    const float* b1 = (const float*)d_in[6];
    const float* W2 = (const float*)d_in[7];
    const float* b2 = (const float*)d_in[8];

    int B = in_sizes[0] / (BN * LVL);   // 16384
    float* outSigma = (float*)d_out;
    float* outColor = (float*)d_out + (size_t)B * BN;

    int grid = B < 2048 ? B : 2048;
    surf_kernel<<<grid, 128>>>(x, dv, gw, W0, b0, W1, b1, W2, b2,
                               outSigma, outColor, B);
}

// round 3
// speedup vs baseline: 1.3291x; 1.3291x over previous
#include <cuda_runtime.h>
#include <math.h>

// SurfNetwork fused kernel v2: 2 samples/thread to halve shared-memory
// weight traffic (L1 pipe was the 84.6% binder). fp32 + packed f32x2 FFMA2.

#define BN   128
#define LVL  6
#define DIRD 16
#define HID  64
#define GEO  18     // LVL*3
#define HSTR 65     // padded stride for conflict-free per-thread h rows

typedef unsigned long long u64;

// ---- dynamic smem layout (float offsets) ----
#define OFF_W1    0                    // 4096  W1 (64x64)
#define OFF_W0G   4096                 // 1152  W0 rows 16..33 (geo part)
#define OFF_W0D   5248                 // 1024  W0 rows 0..15 (dir part)
#define OFF_W2    6272                 // 192   W2 (64x3)
#define OFF_B0    6464                 // 64
#define OFF_B1    6528                 // 64
#define OFF_BASE  6592                 // 128   per-row base = b0 + d.W0dir  [2][64]
#define OFF_B2    6720                 // 4
#define OFF_SIG   6724                 // 256   [2][128]
#define OFF_MAX   6980                 // 8     [2][4]
#define OFF_COL   6988                 // 24    [2][4][3]
#define OFF_H     7012                 // 2*128*65 = 16640
#define SMEM_FLOATS (OFF_H + 2*128*HSTR)
#define SMEM_BYTES  (SMEM_FLOATS * 4)  // 94608

__device__ __forceinline__ u64 pk2(float v) {
    u64 r; asm("mov.b64 %0,{%1,%2};" : "=l"(r) : "f"(v), "f"(v)); return r;
}
__device__ __forceinline__ u64 ffma2(u64 a, u64 b, u64 c) {
    u64 d; asm("fma.rn.f32x2 %0,%1,%2,%3;" : "=l"(d) : "l"(a), "l"(b), "l"(c)); return d;
}
__device__ __forceinline__ void upk2(u64 a, float& lo, float& hi) {
    asm("mov.b64 {%0,%1},%2;" : "=f"(lo), "=f"(hi) : "l"(a));
}

__global__ void __launch_bounds__(128, 2)
surf_kernel2(const int* __restrict__ x,
             const float* __restrict__ dvec,
             const float4* __restrict__ gw,
             const float* __restrict__ W0, const float* __restrict__ b0,
             const float* __restrict__ W1, const float* __restrict__ b1,
             const float* __restrict__ W2, const float* __restrict__ b2,
             float* __restrict__ outSigma, float* __restrict__ outColor,
             int B)
{
    extern __shared__ float sm[];
    const int tid  = threadIdx.x;
    const int lane = tid & 31;
    const int warp = tid >> 5;

    // ---- stage weights once per block ----
    for (int i = tid; i < HID * HID; i += 128) sm[OFF_W1 + i]  = W1[i];
    for (int i = tid; i < GEO * HID; i += 128) sm[OFF_W0G + i] = W0[DIRD * HID + i];
    for (int i = tid; i < DIRD * HID; i += 128) sm[OFF_W0D + i] = W0[i];
    for (int i = tid; i < HID * 3;   i += 128) sm[OFF_W2 + i]  = W2[i];
    if (tid < HID) { sm[OFF_B0 + tid] = b0[tid]; sm[OFF_B1 + tid] = b1[tid]; }
    if (tid < 3)   sm[OFF_B2 + tid] = b2[tid];
    __syncthreads();

    float* h0p = sm + OFF_H + tid * HSTR;             // this thread's h, sample 0
    float* h1p = sm + OFF_H + 128 * HSTR + tid * HSTR; // sample 1

    const int pairs = B >> 1;
    for (int p = blockIdx.x; p < pairs; p += gridDim.x) {
        const int r0 = 2 * p, r1 = 2 * p + 1;

        // per-row base = b0 + d[row] . W0[:16,:]   (threads 0..63 row0, 64..127 row1)
        {
            const int s = tid >> 6, j = tid & 63;
            float acc = sm[OFF_B0 + j];
            const float* dd = dvec + (size_t)(2 * p + s) * DIRD;
            #pragma unroll
            for (int i = 0; i < DIRD; i++)
                acc = fmaf(__ldg(dd + i), sm[OFF_W0D + i * HID + j], acc);
            sm[OFF_BASE + s * HID + j] = acc;
        }

        // ---- gather for both samples ----
        float g0[GEO], g1[GEO];
        float sg0 = 1.0f, sg1 = 1.0f;
        const int* xp0 = x + ((size_t)r0 * BN + tid) * LVL;
        const int* xp1 = x + ((size_t)r1 * BN + tid) * LVL;
        #pragma unroll
        for (int l = 0; l < LVL; l++) {
            float4 f0 = __ldg(gw + __ldg(xp0 + l));
            sg0 *= fminf(fmaxf(f0.x, 0.0f), 1.0f);
            g0[3*l] = f0.y; g0[3*l+1] = f0.z; g0[3*l+2] = f0.w;
            float4 f1 = __ldg(gw + __ldg(xp1 + l));
            sg1 *= fminf(fmaxf(f1.x, 0.0f), 1.0f);
            g1[3*l] = f1.y; g1[3*l+1] = f1.z; g1[3*l+2] = f1.w;
        }
        sg0 += 1e-4f; sg1 += 1e-4f;
        sm[OFF_SIG + tid] = sg0;
        sm[OFF_SIG + 128 + tid] = sg1;

        float m0 = sg0, m1 = sg1;
        #pragma unroll
        for (int o = 16; o; o >>= 1) {
            m0 = fmaxf(m0, __shfl_xor_sync(0xffffffffu, m0, o));
            m1 = fmaxf(m1, __shfl_xor_sync(0xffffffffu, m1, o));
        }
        if (lane == 0) { sm[OFF_MAX + warp] = m0; sm[OFF_MAX + 4 + warp] = m1; }
        __syncthreads();   // (A) publishes sBase, sSig, sMax
        m0 = fmaxf(fmaxf(sm[OFF_MAX+0], sm[OFF_MAX+1]), fmaxf(sm[OFF_MAX+2], sm[OFF_MAX+3]));
        m1 = fmaxf(fmaxf(sm[OFF_MAX+4], sm[OFF_MAX+5]), fmaxf(sm[OFF_MAX+6], sm[OFF_MAX+7]));

        float sig0 = sg0 / m0, sig1 = sg1 / m1;
        outSigma[(size_t)r0 * BN + tid] = sig0;
        outSigma[(size_t)r1 * BN + tid] = sig1;
        float tb0 = tid ? 1.0f - sm[OFF_SIG + tid - 1] / m0 : 1.0f;
        float tb1 = tid ? 1.0f - sm[OFF_SIG + 128 + tid - 1] / m1 : 1.0f;
        float cw0 = tb0 * sig0, cw1 = tb1 * sig1;

        // ---- layer 0: a = base + geo . W0geo  (weights shared by both samples) ----
        u64 a0[HID/2], a1[HID/2];
        {
            const u64* bp0 = (const u64*)(sm + OFF_BASE);
            const u64* bp1 = (const u64*)(sm + OFF_BASE + HID);
            #pragma unroll
            for (int j = 0; j < HID/2; j++) { a0[j] = bp0[j]; a1[j] = bp1[j]; }
        }
        #pragma unroll
        for (int i = 0; i < GEO; i++) {
            u64 x0 = pk2(g0[i]), x1 = pk2(g1[i]);
            const ulonglong2* w = (const ulonglong2*)(sm + OFF_W0G + i * HID);
            #pragma unroll
            for (int jj = 0; jj < HID/4; jj++) {
                ulonglong2 ww = w[jj];
                a0[2*jj]   = ffma2(x0, ww.x, a0[2*jj]);
                a0[2*jj+1] = ffma2(x0, ww.y, a0[2*jj+1]);
                a1[2*jj]   = ffma2(x1, ww.x, a1[2*jj]);
                a1[2*jj+1] = ffma2(x1, ww.y, a1[2*jj+1]);
            }
        }
        // relu -> per-thread h rows in smem (private, no sync needed)
        #pragma unroll
        for (int j = 0; j < HID/2; j++) {
            float lo, hi;
            upk2(a0[j], lo, hi);
            h0p[2*j] = fmaxf(lo, 0.0f); h0p[2*j+1] = fmaxf(hi, 0.0f);
            upk2(a1[j], lo, hi);
            h1p[2*j] = fmaxf(lo, 0.0f); h1p[2*j+1] = fmaxf(hi, 0.0f);
        }

        // ---- layer 1: weights shared by both samples ----
        {
            const u64* bb = (const u64*)(sm + OFF_B1);
            #pragma unroll
            for (int j = 0; j < HID/2; j++) { u64 v = bb[j]; a0[j] = v; a1[j] = v; }
        }
        #pragma unroll 2
        for (int i = 0; i < HID; i++) {
            u64 x0 = pk2(h0p[i]), x1 = pk2(h1p[i]);
            const ulonglong2* w = (const ulonglong2*)(sm + OFF_W1 + i * HID);
            #pragma unroll
            for (int jj = 0; jj < HID/4; jj++) {
                ulonglong2 ww = w[jj];
                a0[2*jj]   = ffma2(x0, ww.x, a0[2*jj]);
                a0[2*jj+1] = ffma2(x0, ww.y, a0[2*jj+1]);
                a1[2*jj]   = ffma2(x1, ww.x, a1[2*jj]);
                a1[2*jj+1] = ffma2(x1, ww.y, a1[2*jj+1]);
            }
        }

        // ---- layer 2 fused with relu-unpack (weights shared) ----
        float l00 = sm[OFF_B2], l01 = sm[OFF_B2+1], l02 = sm[OFF_B2+2];
        float l10 = l00, l11 = l01, l12 = l02;
        #pragma unroll
        for (int j = 0; j < HID/2; j++) {
            float w0a = sm[OFF_W2 + 6*j + 0], w1a = sm[OFF_W2 + 6*j + 1], w2a = sm[OFF_W2 + 6*j + 2];
            float w0b = sm[OFF_W2 + 6*j + 3], w1b = sm[OFF_W2 + 6*j + 4], w2b = sm[OFF_W2 + 6*j + 5];
            float lo, hi;
            upk2(a0[j], lo, hi);
            lo = fmaxf(lo, 0.0f); hi = fmaxf(hi, 0.0f);
            l00 = fmaf(lo, w0a, l00); l01 = fmaf(lo, w1a, l01); l02 = fmaf(lo, w2a, l02);
            l00 = fmaf(hi, w0b, l00); l01 = fmaf(hi, w1b, l01); l02 = fmaf(hi, w2b, l02);
            upk2(a1[j], lo, hi);
            lo = fmaxf(lo, 0.0f); hi = fmaxf(hi, 0.0f);
            l10 = fmaf(lo, w0a, l10); l11 = fmaf(lo, w1a, l11); l12 = fmaf(lo, w2a, l12);
            l10 = fmaf(hi, w0b, l10); l11 = fmaf(hi, w1b, l11); l12 = fmaf(hi, w2b, l12);
        }
        float c00 = 1.0f / (1.0f + expf(-l00));
        float c01 = 1.0f / (1.0f + expf(-l01));
        float c02 = 1.0f / (1.0f + expf(-l02));
        float c10 = 1.0f / (1.0f + expf(-l10));
        float c11 = 1.0f / (1.0f + expf(-l11));
        float c12 = 1.0f / (1.0f + expf(-l12));

        // ---- weighted color reductions (both rows) ----
        float rr0 = cw0 * c00, gg0 = cw0 * c01, bb0 = cw0 * c02;
        float rr1 = cw1 * c10, gg1 = cw1 * c11, bb1 = cw1 * c12;
        #pragma unroll
        for (int o = 16; o; o >>= 1) {
            rr0 += __shfl_xor_sync(0xffffffffu, rr0, o);
            gg0 += __shfl_xor_sync(0xffffffffu, gg0, o);
            bb0 += __shfl_xor_sync(0xffffffffu, bb0, o);
            rr1 += __shfl_xor_sync(0xffffffffu, rr1, o);
            gg1 += __shfl_xor_sync(0xffffffffu, gg1, o);
            bb1 += __shfl_xor_sync(0xffffffffu, bb1, o);
        }
        if (lane == 0) {
            sm[OFF_COL + warp*3 + 0] = rr0;
            sm[OFF_COL + warp*3 + 1] = gg0;
            sm[OFF_COL + warp*3 + 2] = bb0;
            sm[OFF_COL + 12 + warp*3 + 0] = rr1;
            sm[OFF_COL + 12 + warp*3 + 1] = gg1;
            sm[OFF_COL + 12 + warp*3 + 2] = bb1;
        }
        __syncthreads();   // (B) publishes sCol
        if (tid < 6) {
            const int s = tid / 3, c = tid % 3;
            const float* cp = sm + OFF_COL + s * 12;
            outColor[(size_t)(2 * p + s) * 3 + c] =
                cp[c] + cp[3 + c] + cp[6 + c] + cp[9 + c];
        }
        // next iteration's writes to sBase/sSig/sMax are gated by sync (A);
        // sCol rewritten only after next sync (A) — no extra sync needed here.
    }
}

extern "C" void kernel_launch(void* const* d_in, const int* in_sizes, int n_in,
                              void* d_out, int out_size)
{
    const int*    x  = (const int*)d_in[0];
    const float*  dv = (const float*)d_in[1];
    const float4* gw = (const float4*)d_in[2];
    const float*  W0 = (const float*)d_in[3];
    const float*  b0 = (const float*)d_in[4];
    const float*  W1 = (const float*)d_in[5];
    const float*  b1 = (const float*)d_in[6];
    const float*  W2 = (const float*)d_in[7];
    const float*  b2 = (const float*)d_in[8];

    const int B = in_sizes[0] / (BN * LVL);   // 16384
    float* outSigma = (float*)d_out;
    float* outColor = (float*)d_out + (size_t)B * BN;

    cudaFuncSetAttribute(surf_kernel2,
                         cudaFuncAttributeMaxDynamicSharedMemorySize, SMEM_BYTES);

    const int pairs = B >> 1;
    int grid = pairs < 304 ? pairs : 304;   // 2 blocks/SM resident, persistent loop
    surf_kernel2<<<grid, 128, SMEM_BYTES>>>(x, dv, gw, W0, b0, W1, b1, W2, b2,
                                            outSigma, outColor, B);
}

// round 4
// speedup vs baseline: 2.1792x; 1.6396x over previous
#include <cuda_runtime.h>
#include <math.h>

// SurfNetwork v3: MLP on tensor cores via mma.sync m16n8k8 tf32.
// Block = 128 threads (4 warps) handles one batch row (128 samples) per iter.
// Warp w owns samples [32w, 32w+32). Activations live in SMEM (stride 72,
// row&4 XOR-4 swizzle -> conflict-free frag loads/stores). Sigma path fp32 exact.

#define BN   128
#define LVL  6
#define DIRD 16
#define GEO  18
#define SGG  25    // geo buffer stride (24 cols used, odd stride)
#define SH   72    // activation buffer stride (bank-free with swizzle)
#define SCBS 9     // color logit buffer stride

typedef unsigned int u32;

// ---- dynamic smem layout (float offsets) ----
#define O_W0G   0        // 24x72 tf32 (W0 rows 16..33, zero-padded to 24)
#define O_W1    1728     // 64x72 tf32
#define O_W2    6336     // 64x8  tf32 (cols 3..7 zero)
#define O_W0D   6848     // 16x64 fp32 (dir part for base)
#define O_B0    7872     // 64
#define O_B1    7936     // 64
#define O_B2    8000     // 8 (pad)
#define O_BASE  8008     // 64
#define O_SIG   8072     // 128
#define O_MAX   8200     // 4
#define O_COL   8204     // 12
#define O_ACTG  8216     // 128x25 (tf32 geo, cols 18..24 zeroed once)
#define O_ACTH  11416    // 128x72 (tf32 activations)
#define O_COLB  20632    // 128x9  (fp32 logits)
#define SMEM_FLOATS 21784
#define SMEM_BYTES  (SMEM_FLOATS * 4)   // 87136 B -> 2 blocks/SM

__device__ __forceinline__ u32 tf32r(float f) {
    u32 u; asm("cvt.rna.tf32.f32 %0, %1;" : "=r"(u) : "f"(f)); return u;
}
__device__ __forceinline__ void mma8(float* c, const u32* a, u32 b0, u32 b1) {
    asm volatile(
        "mma.sync.aligned.m16n8k8.row.col.f32.tf32.tf32.f32 "
        "{%0,%1,%2,%3},{%4,%5,%6,%7},{%8,%9},{%0,%1,%2,%3};"
        : "+f"(c[0]), "+f"(c[1]), "+f"(c[2]), "+f"(c[3])
        : "r"(a[0]), "r"(a[1]), "r"(a[2]), "r"(a[3]), "r"(b0), "r"(b1));
}

__global__ void __launch_bounds__(128, 2)
surf_mma(const int* __restrict__ x,
         const float* __restrict__ dvec,
         const float4* __restrict__ gw,
         const float* __restrict__ W0, const float* __restrict__ b0,
         const float* __restrict__ W1, const float* __restrict__ b1,
         const float* __restrict__ W2, const float* __restrict__ b2,
         float* __restrict__ outSigma, float* __restrict__ outColor,
         int B)
{
    extern __shared__ float sm[];
    const int tid  = threadIdx.x;
    const int lane = tid & 31;
    const int warp = tid >> 5;
    const int grp  = lane >> 2;     // 0..7
    const int tig  = lane & 3;      // 0..3
    const int sw   = grp & 4;       // activation-row swizzle (row&4 == grp&4 here)

    // ---------- stage weights (tf32) once per block ----------
    {
        u32* wg = (u32*)(sm + O_W0G);
        for (int i = tid; i < 24 * SH; i += 128) {
            int k = i / SH, n = i - k * SH;
            float v = (k < GEO && n < 64) ? W0[(DIRD + k) * 64 + n] : 0.0f;
            wg[i] = tf32r(v);
        }
        u32* w1 = (u32*)(sm + O_W1);
        for (int i = tid; i < 64 * SH; i += 128) {
            int k = i / SH, n = i - k * SH;
            float v = (n < 64) ? W1[k * 64 + n] : 0.0f;
            w1[i] = tf32r(v);
        }
        u32* w2 = (u32*)(sm + O_W2);
        for (int i = tid; i < 64 * 8; i += 128) {
            int k = i >> 3, n = i & 7;
            float v = (n < 3) ? W2[k * 3 + n] : 0.0f;
            w2[i] = tf32r(v);
        }
        for (int i = tid; i < DIRD * 64; i += 128) sm[O_W0D + i] = W0[i];
        if (tid < 64) { sm[O_B0 + tid] = b0[tid]; sm[O_B1 + tid] = b1[tid]; }
        if (tid < 8)  sm[O_B2 + tid] = (tid < 3) ? b2[tid] : 0.0f;
        // zero geo pad columns 18..24 (constant across iterations)
        for (int i = tid; i < 128 * 7; i += 128) {
            int r = i / 7, c = 18 + (i - r * 7);
            sm[O_ACTG + r * SGG + c] = 0.0f;
        }
    }
    __syncthreads();

    for (int row = blockIdx.x; row < B; row += gridDim.x) {
        // ================= phase 1: base + gather + sigma =================
        if (tid < 64) {
            float acc = sm[O_B0 + tid];
            const float* dd = dvec + (size_t)row * DIRD;
            #pragma unroll
            for (int i = 0; i < DIRD; i++)
                acc = fmaf(__ldg(dd + i), sm[O_W0D + i * 64 + tid], acc);
            sm[O_BASE + tid] = acc;
        }

        const int* xp = x + ((size_t)row * BN + tid) * LVL;
        float geo[GEO];
        float sg = 1.0f;
        #pragma unroll
        for (int l = 0; l < LVL; l++) {
            float4 f = __ldg(gw + __ldg(xp + l));
            sg *= fminf(fmaxf(f.x, 0.0f), 1.0f);
            geo[3 * l] = f.y; geo[3 * l + 1] = f.z; geo[3 * l + 2] = f.w;
        }
        sg += 1e-4f;
        sm[O_SIG + tid] = sg;
        {   // geo -> tf32 -> ActG row tid
            u32* ag = (u32*)(sm + O_ACTG) + tid * SGG;
            #pragma unroll
            for (int j = 0; j < GEO; j++) ag[j] = tf32r(geo[j]);
        }
        float m = sg;
        #pragma unroll
        for (int o = 16; o; o >>= 1) m = fmaxf(m, __shfl_xor_sync(0xffffffffu, m, o));
        if (lane == 0) sm[O_MAX + warp] = m;
        __syncthreads();   // (A)
        m = fmaxf(fmaxf(sm[O_MAX + 0], sm[O_MAX + 1]), fmaxf(sm[O_MAX + 2], sm[O_MAX + 3]));

        float sigma = sg / m;
        outSigma[(size_t)row * BN + tid] = sigma;
        float tb = tid ? 1.0f - sm[O_SIG + tid - 1] / m : 1.0f;
        float cw = tb * sigma;

        // ================= phase 2: MLP on tensor cores =================
        // ----- layer 0: ActG(128x24) @ W0g(24x64) + base -> ActH -----
        #pragma unroll
        for (int mt = 0; mt < 2; mt++) {
            const int r0 = warp * 32 + mt * 16;
            const int rA = r0 + grp, rB = rA + 8;
            u32 a[3][4];
            const u32* AG = (const u32*)(sm + O_ACTG);
            #pragma unroll
            for (int k = 0; k < 3; k++) {
                int c0 = k * 8 + tig;
                a[k][0] = AG[rA * SGG + c0];
                a[k][1] = AG[rB * SGG + c0];
                a[k][2] = AG[rA * SGG + c0 + 4];
                a[k][3] = AG[rB * SGG + c0 + 4];
            }
            float C[8][4];
            #pragma unroll
            for (int n = 0; n < 8; n++) {
                float v0 = sm[O_BASE + n * 8 + 2 * tig];
                float v1 = sm[O_BASE + n * 8 + 2 * tig + 1];
                C[n][0] = v0; C[n][1] = v1; C[n][2] = v0; C[n][3] = v1;
            }
            const u32* WG = (const u32*)(sm + O_W0G);
            #pragma unroll
            for (int n = 0; n < 8; n++)
                #pragma unroll
                for (int k = 0; k < 3; k++) {
                    u32 bb0 = WG[(k * 8 + tig) * SH + n * 8 + grp];
                    u32 bb1 = WG[(k * 8 + tig + 4) * SH + n * 8 + grp];
                    mma8(C[n], a[k], bb0, bb1);
                }
            u32* AH = (u32*)(sm + O_ACTH);
            #pragma unroll
            for (int n = 0; n < 8; n++) {
                int col = (n * 8 + 2 * tig) ^ sw;
                uint2 lo = make_uint2(tf32r(fmaxf(C[n][0], 0.0f)), tf32r(fmaxf(C[n][1], 0.0f)));
                uint2 hi = make_uint2(tf32r(fmaxf(C[n][2], 0.0f)), tf32r(fmaxf(C[n][3], 0.0f)));
                *(uint2*)(AH + rA * SH + col) = lo;
                *(uint2*)(AH + rB * SH + col) = hi;
            }
        }
        __syncwarp();

        // ----- layer 1: ActH(128x64) @ W1(64x64) -> ActH (in-place per tile) -----
        #pragma unroll
        for (int mt = 0; mt < 2; mt++) {
            const int r0 = warp * 32 + mt * 16;
            const int rA = r0 + grp, rB = rA + 8;
            u32 a[8][4];
            const u32* AH = (const u32*)(sm + O_ACTH);
            #pragma unroll
            for (int k = 0; k < 8; k++) {
                int cL = k * 8 + (tig ^ sw);
                int cH = k * 8 + (tig ^ sw ^ 4);
                a[k][0] = AH[rA * SH + cL];
                a[k][1] = AH[rB * SH + cL];
                a[k][2] = AH[rA * SH + cH];
                a[k][3] = AH[rB * SH + cH];
            }
            float C[8][4];
            #pragma unroll
            for (int n = 0; n < 8; n++) {
                float v0 = sm[O_B1 + n * 8 + 2 * tig];
                float v1 = sm[O_B1 + n * 8 + 2 * tig + 1];
                C[n][0] = v0; C[n][1] = v1; C[n][2] = v0; C[n][3] = v1;
            }
            const u32* W1s = (const u32*)(sm + O_W1);
            #pragma unroll
            for (int n = 0; n < 8; n++)
                #pragma unroll
                for (int k = 0; k < 8; k++) {
                    u32 bb0 = W1s[(k * 8 + tig) * SH + n * 8 + grp];
                    u32 bb1 = W1s[(k * 8 + tig + 4) * SH + n * 8 + grp];
                    mma8(C[n], a[k], bb0, bb1);
                }
            __syncwarp();   // all lanes' A-loads done before in-place overwrite
            u32* AHw = (u32*)(sm + O_ACTH);
            #pragma unroll
            for (int n = 0; n < 8; n++) {
                int col = (n * 8 + 2 * tig) ^ sw;
                uint2 lo = make_uint2(tf32r(fmaxf(C[n][0], 0.0f)), tf32r(fmaxf(C[n][1], 0.0f)));
                uint2 hi = make_uint2(tf32r(fmaxf(C[n][2], 0.0f)), tf32r(fmaxf(C[n][3], 0.0f)));
                *(uint2*)(AHw + rA * SH + col) = lo;
                *(uint2*)(AHw + rB * SH + col) = hi;
            }
        }
        __syncwarp();

        // ----- layer 2: ActH(128x64) @ W2(64x8) -> logits in ColB -----
        #pragma unroll
        for (int mt = 0; mt < 2; mt++) {
            const int r0 = warp * 32 + mt * 16;
            const int rA = r0 + grp, rB = rA + 8;
            u32 a[8][4];
            const u32* AH = (const u32*)(sm + O_ACTH);
            #pragma unroll
            for (int k = 0; k < 8; k++) {
                int cL = k * 8 + (tig ^ sw);
                int cH = k * 8 + (tig ^ sw ^ 4);
                a[k][0] = AH[rA * SH + cL];
                a[k][1] = AH[rB * SH + cL];
                a[k][2] = AH[rA * SH + cH];
                a[k][3] = AH[rB * SH + cH];
            }
            float C2[4];
            C2[0] = sm[O_B2 + 2 * tig];
            C2[1] = sm[O_B2 + 2 * tig + 1];
            C2[2] = C2[0]; C2[3] = C2[1];
            const u32* W2s = (const u32*)(sm + O_W2);
            #pragma unroll
            for (int k = 0; k < 8; k++) {
                u32 bb0 = W2s[(k * 8 + tig) * 8 + grp];
                u32 bb1 = W2s[(k * 8 + tig + 4) * 8 + grp];
                mma8(C2, a[k], bb0, bb1);
            }
            if (2 * tig < 3) {
                sm[O_COLB + rA * SCBS + 2 * tig] = C2[0];
                sm[O_COLB + rB * SCBS + 2 * tig] = C2[2];
            }
            if (2 * tig + 1 < 3) {
                sm[O_COLB + rA * SCBS + 2 * tig + 1] = C2[1];
                sm[O_COLB + rB * SCBS + 2 * tig + 1] = C2[3];
            }
        }
        __syncwarp();   // ColB rows are warp-private; order stores before reads

        // ================= phase 3: sigmoid + weighted reduction =================
        float l0 = sm[O_COLB + tid * SCBS + 0];
        float l1 = sm[O_COLB + tid * SCBS + 1];
        float l2 = sm[O_COLB + tid * SCBS + 2];
        float c0 = 1.0f / (1.0f + expf(-l0));
        float c1 = 1.0f / (1.0f + expf(-l1));
        float c2 = 1.0f / (1.0f + expf(-l2));
        float rr = cw * c0, gg = cw * c1, bb = cw * c2;
        #pragma unroll
        for (int o = 16; o; o >>= 1) {
            rr += __shfl_xor_sync(0xffffffffu, rr, o);
            gg += __shfl_xor_sync(0xffffffffu, gg, o);
            bb += __shfl_xor_sync(0xffffffffu, bb, o);
        }
        if (lane == 0) {
            sm[O_COL + warp * 3 + 0] = rr;
            sm[O_COL + warp * 3 + 1] = gg;
            sm[O_COL + warp * 3 + 2] = bb;
        }
        __syncthreads();   // (C) — also gates next iteration's smem writes
        if (tid < 3) {
            outColor[(size_t)row * 3 + tid] =
                sm[O_COL + tid] + sm[O_COL + 3 + tid] +
                sm[O_COL + 6 + tid] + sm[O_COL + 9 + tid];
        }
    }
}

extern "C" void kernel_launch(void* const* d_in, const int* in_sizes, int n_in,
                              void* d_out, int out_size)
{
    const int*    x  = (const int*)d_in[0];
    const float*  dv = (const float*)d_in[1];
    const float4* gw = (const float4*)d_in[2];
    const float*  W0 = (const float*)d_in[3];
    const float*  b0 = (const float*)d_in[4];
    const float*  W1 = (const float*)d_in[5];
    const float*  b1 = (const float*)d_in[6];
    const float*  W2 = (const float*)d_in[7];
    const float*  b2 = (const float*)d_in[8];

    const int B = in_sizes[0] / (BN * LVL);   // 16384
    float* outSigma = (float*)d_out;
    float* outColor = (float*)d_out + (size_t)B * BN;

    cudaFuncSetAttribute(surf_mma,
                         cudaFuncAttributeMaxDynamicSharedMemorySize, SMEM_BYTES);

    int grid = B < 296 ? B : 296;   // 2 blocks/SM persistent
    surf_mma<<<grid, 128, SMEM_BYTES>>>(x, dv, gw, W0, b0, W1, b1, W2, b2,
                                        outSigma, outColor, B);
}

// round 5
// speedup vs baseline: 2.4579x; 1.1279x over previous
#include <cuda_runtime.h>
#include <cuda_bf16.h>
#include <math.h>

// SurfNetwork v4: MLP on bf16 tensor cores (mma.sync m16n8k16), fp32 accum.
// 128 threads/block, 4 blocks/SM (smem ~54KB). Per iteration one batch row
// (128 samples); warp w owns rows [32w,32w+32). Weights stored transposed
// (n-major, k-pairs packed bf16x2) at stride==4 (mod 32) -> bank-conflict-free
// B-fragment loads. Sigma path exact fp32.

#define BN   128
#define LVL  6
#define DIRD 16
#define GEO  18

#define SW0G 20    // W0geo^T row stride (u32)
#define SW1  36    // W1^T row stride
#define SW2  36    // W2^T row stride
#define SAG  20    // ActG row stride
#define SAH  36    // ActH row stride
#define SCB  9     // ColB row stride (f32)

typedef unsigned int u32;

// ---- smem layout (4-byte word offsets) ----
#define O_W0GT 0                  // 64*20
#define O_W1T  1280               // 64*36
#define O_W2T  3584               // 8*36
#define O_W0D  3872               // 16*64 fp32
#define O_B0   4896               // 64
#define O_B1   4960               // 64
#define O_B2   5024               // 8
#define O_BASE 5032               // 64
#define O_SIG  5096               // 128
#define O_MAX  5224               // 4
#define O_COL  5228               // 12
#define O_ACTG 5240               // 128*20 (bf16x2)
#define O_ACTH 7800               // 128*36 (bf16x2)
#define O_COLB 12408              // 128*9 fp32
#define SMEM_WORDS 13560
#define SMEM_BYTES (SMEM_WORDS * 4)   // 54240

__device__ __forceinline__ u32 pkbf(float lo, float hi) {
    u32 r; asm("cvt.rn.bf16x2.f32 %0, %1, %2;" : "=r"(r) : "f"(hi), "f"(lo));
    return r;
}
__device__ __forceinline__ void mma16(float* c, const u32* a, u32 b0, u32 b1) {
    asm volatile(
        "mma.sync.aligned.m16n8k16.row.col.f32.bf16.bf16.f32 "
        "{%0,%1,%2,%3},{%4,%5,%6,%7},{%8,%9},{%0,%1,%2,%3};"
        : "+f"(c[0]), "+f"(c[1]), "+f"(c[2]), "+f"(c[3])
        : "r"(a[0]), "r"(a[1]), "r"(a[2]), "r"(a[3]), "r"(b0), "r"(b1));
}
// ActG physical slot: XOR swizzle kills 4-way write conflicts (rows tid,tid+8,..)
__device__ __forceinline__ int agix(int row, int j) {
    return row * SAG + (j ^ ((row >> 3) & 3));
}

__global__ void __launch_bounds__(128, 4)
surf_bf16(const int* __restrict__ x,
          const float* __restrict__ dvec,
          const float4* __restrict__ gw,
          const float* __restrict__ W0, const float* __restrict__ b0,
          const float* __restrict__ W1, const float* __restrict__ b1,
          const float* __restrict__ W2, const float* __restrict__ b2,
          float* __restrict__ outSigma, float* __restrict__ outColor,
          int B)
{
    extern __shared__ float sm[];
    u32* smu = (u32*)sm;
    const int tid  = threadIdx.x;
    const int lane = tid & 31;
    const int warp = tid >> 5;
    const int grp  = lane >> 2;   // 0..7
    const int tig  = lane & 3;    // 0..3

    // ---------- stage weights (transposed, bf16x2 pairs) ----------
    // W0geo^T: row n (0..63), pair kk (0..15) -> {W0[16+2kk][n], W0[16+2kk+1][n]}
    for (int i = tid; i < 64 * SW0G; i += 128) {
        int n = i / SW0G, kk = i - n * SW0G;
        u32 v = 0;
        if (kk < 16) {
            int g0 = 2 * kk, g1 = 2 * kk + 1;
            float lo = (g0 < GEO) ? W0[(DIRD + g0) * 64 + n] : 0.0f;
            float hi = (g1 < GEO) ? W0[(DIRD + g1) * 64 + n] : 0.0f;
            v = pkbf(lo, hi);
        }
        smu[O_W0GT + i] = v;
    }
    // W1^T: row n, pair kk (0..31) -> {W1[2kk][n], W1[2kk+1][n]}
    for (int i = tid; i < 64 * SW1; i += 128) {
        int n = i / SW1, kk = i - n * SW1;
        u32 v = 0;
        if (kk < 32) v = pkbf(W1[(2 * kk) * 64 + n], W1[(2 * kk + 1) * 64 + n]);
        smu[O_W1T + i] = v;
    }
    // W2^T: row n (0..7, cols>=3 zero), pair kk (0..31)
    for (int i = tid; i < 8 * SW2; i += 128) {
        int n = i / SW2, kk = i - n * SW2;
        u32 v = 0;
        if (kk < 32 && n < 3) v = pkbf(W2[(2 * kk) * 3 + n], W2[(2 * kk + 1) * 3 + n]);
        smu[O_W2T + i] = v;
    }
    for (int i = tid; i < DIRD * 64; i += 128) sm[O_W0D + i] = W0[i];
    if (tid < 64) { sm[O_B0 + tid] = b0[tid]; sm[O_B1 + tid] = b1[tid]; }
    if (tid < 8)  sm[O_B2 + tid] = (tid < 3) ? b2[tid] : 0.0f;
    // zero ActG pad slots (logical j 9..15), once
    for (int r = 0; r < 1; r++)
        for (int j = 9; j < 16; j++) smu[O_ACTG + agix(tid, j)] = 0;
    __syncthreads();

    for (int row = blockIdx.x; row < B; row += gridDim.x) {
        // ============ phase 1: base, gather, sigma ============
        if (tid < 64) {
            float acc = sm[O_B0 + tid];
            const float* dd = dvec + (size_t)row * DIRD;
            #pragma unroll
            for (int i = 0; i < DIRD; i++)
                acc = fmaf(__ldg(dd + i), sm[O_W0D + i * 64 + tid], acc);
            sm[O_BASE + tid] = acc;
        }
        const int* xp = x + ((size_t)row * BN + tid) * LVL;
        float geo[GEO];
        float sg = 1.0f;
        #pragma unroll
        for (int l = 0; l < LVL; l++) {
            float4 f = __ldg(gw + __ldg(xp + l));
            sg *= fminf(fmaxf(f.x, 0.0f), 1.0f);
            geo[3 * l] = f.y; geo[3 * l + 1] = f.z; geo[3 * l + 2] = f.w;
        }
        sg += 1e-4f;
        sm[O_SIG + tid] = sg;
        #pragma unroll
        for (int j = 0; j < 9; j++)
            smu[O_ACTG + agix(tid, j)] = pkbf(geo[2 * j], geo[2 * j + 1]);

        float m = sg;
        #pragma unroll
        for (int o = 16; o; o >>= 1) m = fmaxf(m, __shfl_xor_sync(0xffffffffu, m, o));
        if (lane == 0) sm[O_MAX + warp] = m;
        __syncthreads();   // (A) publishes BASE/SIG/MAX/ActG
        m = fmaxf(fmaxf(sm[O_MAX + 0], sm[O_MAX + 1]), fmaxf(sm[O_MAX + 2], sm[O_MAX + 3]));

        float sigma = sg / m;
        outSigma[(size_t)row * BN + tid] = sigma;
        float tb = tid ? 1.0f - sm[O_SIG + tid - 1] / m : 1.0f;
        float cw = tb * sigma;

        const int r0 = warp * 32 + grp;   // m-tile 0 row A
        const int r1 = r0 + 16;           // m-tile 1 row A

        // ============ layer 0: ActG(128x32bf) @ W0g^T -> ActH ============
        {
            u32 A[2][2][4];
            const u32* AG = smu + O_ACTG;
            #pragma unroll
            for (int mt = 0; mt < 2; mt++) {
                int rA = r0 + mt * 16, rB = rA + 8;
                #pragma unroll
                for (int k = 0; k < 2; k++) {
                    A[mt][k][0] = AG[agix(rA, k * 8 + tig)];
                    A[mt][k][1] = AG[agix(rB, k * 8 + tig)];
                    A[mt][k][2] = AG[agix(rA, k * 8 + 4 + tig)];
                    A[mt][k][3] = AG[agix(rB, k * 8 + 4 + tig)];
                }
            }
            const u32* WT = smu + O_W0GT;
            u32* AH = smu + O_ACTH;
            #pragma unroll
            for (int n = 0; n < 8; n++) {
                float bv0 = sm[O_BASE + n * 8 + 2 * tig];
                float bv1 = sm[O_BASE + n * 8 + 2 * tig + 1];
                float C0[4] = {bv0, bv1, bv0, bv1};
                float C1[4] = {bv0, bv1, bv0, bv1};
                #pragma unroll
                for (int k = 0; k < 2; k++) {
                    u32 bb0 = WT[(n * 8 + grp) * SW0G + k * 8 + tig];
                    u32 bb1 = WT[(n * 8 + grp) * SW0G + k * 8 + 4 + tig];
                    mma16(C0, A[0][k], bb0, bb1);
                    mma16(C1, A[1][k], bb0, bb1);
                }
                AH[r0 * SAH + n * 4 + tig]        = pkbf(fmaxf(C0[0], 0.f), fmaxf(C0[1], 0.f));
                AH[(r0 + 8) * SAH + n * 4 + tig]  = pkbf(fmaxf(C0[2], 0.f), fmaxf(C0[3], 0.f));
                AH[r1 * SAH + n * 4 + tig]        = pkbf(fmaxf(C1[0], 0.f), fmaxf(C1[1], 0.f));
                AH[(r1 + 8) * SAH + n * 4 + tig]  = pkbf(fmaxf(C1[2], 0.f), fmaxf(C1[3], 0.f));
            }
        }
        __syncwarp();

        // ============ layer 1: ActH @ W1^T -> ActH (in-place) ============
        {
            u32 A[2][4][4];
            const u32* AH = smu + O_ACTH;
            #pragma unroll
            for (int mt = 0; mt < 2; mt++) {
                int rA = r0 + mt * 16, rB = rA + 8;
                #pragma unroll
                for (int k = 0; k < 4; k++) {
                    A[mt][k][0] = AH[rA * SAH + k * 8 + tig];
                    A[mt][k][1] = AH[rB * SAH + k * 8 + tig];
                    A[mt][k][2] = AH[rA * SAH + k * 8 + 4 + tig];
                    A[mt][k][3] = AH[rB * SAH + k * 8 + 4 + tig];
                }
            }
            __syncwarp();   // all lanes' A loads before in-place overwrite
            const u32* WT = smu + O_W1T;
            u32* AHw = smu + O_ACTH;
            #pragma unroll
            for (int n = 0; n < 8; n++) {
                float bv0 = sm[O_B1 + n * 8 + 2 * tig];
                float bv1 = sm[O_B1 + n * 8 + 2 * tig + 1];
                float C0[4] = {bv0, bv1, bv0, bv1};
                float C1[4] = {bv0, bv1, bv0, bv1};
                #pragma unroll
                for (int k = 0; k < 4; k++) {
                    u32 bb0 = WT[(n * 8 + grp) * SW1 + k * 8 + tig];
                    u32 bb1 = WT[(n * 8 + grp) * SW1 + k * 8 + 4 + tig];
                    mma16(C0, A[0][k], bb0, bb1);
                    mma16(C1, A[1][k], bb0, bb1);
                }
                AHw[r0 * SAH + n * 4 + tig]       = pkbf(fmaxf(C0[0], 0.f), fmaxf(C0[1], 0.f));
                AHw[(r0 + 8) * SAH + n * 4 + tig] = pkbf(fmaxf(C0[2], 0.f), fmaxf(C0[3], 0.f));
                AHw[r1 * SAH + n * 4 + tig]       = pkbf(fmaxf(C1[0], 0.f), fmaxf(C1[1], 0.f));
                AHw[(r1 + 8) * SAH + n * 4 + tig] = pkbf(fmaxf(C1[2], 0.f), fmaxf(C1[3], 0.f));
            }
        }
        __syncwarp();

        // ============ layer 2: ActH @ W2^T (n=8 padded) -> logits ============
        {
            u32 A[2][4][4];
            const u32* AH = smu + O_ACTH;
            #pragma unroll
            for (int mt = 0; mt < 2; mt++) {
                int rA = r0 + mt * 16, rB = rA + 8;
                #pragma unroll
                for (int k = 0; k < 4; k++) {
                    A[mt][k][0] = AH[rA * SAH + k * 8 + tig];
                    A[mt][k][1] = AH[rB * SAH + k * 8 + tig];
                    A[mt][k][2] = AH[rA * SAH + k * 8 + 4 + tig];
                    A[mt][k][3] = AH[rB * SAH + k * 8 + 4 + tig];
                }
            }
            const u32* WT = smu + O_W2T;
            float bv0 = sm[O_B2 + 2 * tig];
            float bv1 = sm[O_B2 + 2 * tig + 1];
            float C0[4] = {bv0, bv1, bv0, bv1};
            float C1[4] = {bv0, bv1, bv0, bv1};
            #pragma unroll
            for (int k = 0; k < 4; k++) {
                u32 bb0 = WT[grp * SW2 + k * 8 + tig];
                u32 bb1 = WT[grp * SW2 + k * 8 + 4 + tig];
                mma16(C0, A[0][k], bb0, bb1);
                mma16(C1, A[1][k], bb0, bb1);
            }
            if (2 * tig < 3) {
                sm[O_COLB + r0 * SCB + 2 * tig]        = C0[0];
                sm[O_COLB + (r0 + 8) * SCB + 2 * tig]  = C0[2];
                sm[O_COLB + r1 * SCB + 2 * tig]        = C1[0];
                sm[O_COLB + (r1 + 8) * SCB + 2 * tig]  = C1[2];
            }
            if (2 * tig + 1 < 3) {
                sm[O_COLB + r0 * SCB + 2 * tig + 1]       = C0[1];
                sm[O_COLB + (r0 + 8) * SCB + 2 * tig + 1] = C0[3];
                sm[O_COLB + r1 * SCB + 2 * tig + 1]       = C1[1];
                sm[O_COLB + (r1 + 8) * SCB + 2 * tig + 1] = C1[3];
            }
        }
        __syncwarp();

        // ============ phase 3: sigmoid + weighted color reduction ============
        float l0 = sm[O_COLB + tid * SCB + 0];
        float l1 = sm[O_COLB + tid * SCB + 1];
        float l2 = sm[O_COLB + tid * SCB + 2];
        float c0 = 1.0f / (1.0f + expf(-l0));
        float c1 = 1.0f / (1.0f + expf(-l1));
        float c2 = 1.0f / (1.0f + expf(-l2));
        float rr = cw * c0, gg = cw * c1, bb = cw * c2;
        #pragma unroll
        for (int o = 16; o; o >>= 1) {
            rr += __shfl_xor_sync(0xffffffffu, rr, o);
            gg += __shfl_xor_sync(0xffffffffu, gg, o);
            bb += __shfl_xor_sync(0xffffffffu, bb, o);
        }
        if (lane == 0) {
            sm[O_COL + warp * 3 + 0] = rr;
            sm[O_COL + warp * 3 + 1] = gg;
            sm[O_COL + warp * 3 + 2] = bb;
        }
        __syncthreads();   // (C) publishes COL; gates next-iter smem writes
        if (tid < 3) {
            outColor[(size_t)row * 3 + tid] =
                sm[O_COL + tid] + sm[O_COL + 3 + tid] +
                sm[O_COL + 6 + tid] + sm[O_COL + 9 + tid];
        }
    }
}

extern "C" void kernel_launch(void* const* d_in, const int* in_sizes, int n_in,
                              void* d_out, int out_size)
{
    const int*    x  = (const int*)d_in[0];
    const float*  dv = (const float*)d_in[1];
    const float4* gw = (const float4*)d_in[2];
    const float*  W0 = (const float*)d_in[3];
    const float*  b0 = (const float*)d_in[4];
    const float*  W1 = (const float*)d_in[5];
    const float*  b1 = (const float*)d_in[6];
    const float*  W2 = (const float*)d_in[7];
    const float*  b2 = (const float*)d_in[8];

    const int B = in_sizes[0] / (BN * LVL);   // 16384
    float* outSigma = (float*)d_out;
    float* outColor = (float*)d_out + (size_t)B * BN;

    cudaFuncSetAttribute(surf_bf16,
                         cudaFuncAttributeMaxDynamicSharedMemorySize, SMEM_BYTES);

    int grid = B < 592 ? B : 592;   // 4 blocks/SM persistent
    surf_bf16<<<grid, 128, SMEM_BYTES>>>(x, dv, gw, W0, b0, W1, b1, W2, b2,
                                         outSigma, outColor, B);
}

// round 6
// speedup vs baseline: 4.3444x; 1.7676x over previous
#include <cuda_runtime.h>
#include <cuda_bf16.h>
#include <math.h>

// SurfNetwork v5: v4 (bf16 mma m16n8k16) + software-pipelined gather.
// Next row's x/d loads issue right after sync(A); dependent gw gathers issue
// after layer0; results consumed next iteration -> gather latency hidden
// behind ~2000 cycles of tensor work. 3 blocks/SM.

#define BN   128
#define LVL  6
#define DIRD 16
#define GEO  18

#define SW0G 20
#define SW1  36
#define SW2  36
#define SAG  20
#define SAH  36
#define SCB  9

typedef unsigned int u32;

#define O_W0GT 0
#define O_W1T  1280
#define O_W2T  3584
#define O_W0D  3872
#define O_B0   4896
#define O_B1   4960
#define O_B2   5024
#define O_BASE 5032
#define O_SIG  5096
#define O_MAX  5224
#define O_COL  5228
#define O_ACTG 5240
#define O_ACTH 7800
#define O_COLB 12408
#define SMEM_WORDS 13560
#define SMEM_BYTES (SMEM_WORDS * 4)   // 54240

__device__ __forceinline__ u32 pkbf(float lo, float hi) {
    u32 r; asm("cvt.rn.bf16x2.f32 %0, %1, %2;" : "=r"(r) : "f"(hi), "f"(lo));
    return r;
}
__device__ __forceinline__ void mma16(float* c, const u32* a, u32 b0, u32 b1) {
    asm volatile(
        "mma.sync.aligned.m16n8k16.row.col.f32.bf16.bf16.f32 "
        "{%0,%1,%2,%3},{%4,%5,%6,%7},{%8,%9},{%0,%1,%2,%3};"
        : "+f"(c[0]), "+f"(c[1]), "+f"(c[2]), "+f"(c[3])
        : "r"(a[0]), "r"(a[1]), "r"(a[2]), "r"(a[3]), "r"(b0), "r"(b1));
}
__device__ __forceinline__ int agix(int row, int j) {
    return row * SAG + (j ^ ((row >> 3) & 3));
}

__global__ void __launch_bounds__(128, 3)
surf_pipe(const int* __restrict__ x,
          const float* __restrict__ dvec,
          const float4* __restrict__ gw,
          const float* __restrict__ W0, const float* __restrict__ b0,
          const float* __restrict__ W1, const float* __restrict__ b1,
          const float* __restrict__ W2, const float* __restrict__ b2,
          float* __restrict__ outSigma, float* __restrict__ outColor,
          int B)
{
    extern __shared__ float sm[];
    u32* smu = (u32*)sm;
    const int tid  = threadIdx.x;
    const int lane = tid & 31;
    const int warp = tid >> 5;
    const int grp  = lane >> 2;
    const int tig  = lane & 3;

    // ---------- stage weights (transposed, bf16x2) ----------
    for (int i = tid; i < 64 * SW0G; i += 128) {
        int n = i / SW0G, kk = i - n * SW0G;
        u32 v = 0;
        if (kk < 16) {
            int g0 = 2 * kk, g1 = 2 * kk + 1;
            float lo = (g0 < GEO) ? W0[(DIRD + g0) * 64 + n] : 0.0f;
            float hi = (g1 < GEO) ? W0[(DIRD + g1) * 64 + n] : 0.0f;
            v = pkbf(lo, hi);
        }
        smu[O_W0GT + i] = v;
    }
    for (int i = tid; i < 64 * SW1; i += 128) {
        int n = i / SW1, kk = i - n * SW1;
        u32 v = 0;
        if (kk < 32) v = pkbf(W1[(2 * kk) * 64 + n], W1[(2 * kk + 1) * 64 + n]);
        smu[O_W1T + i] = v;
    }
    for (int i = tid; i < 8 * SW2; i += 128) {
        int n = i / SW2, kk = i - n * SW2;
        u32 v = 0;
        if (kk < 32 && n < 3) v = pkbf(W2[(2 * kk) * 3 + n], W2[(2 * kk + 1) * 3 + n]);
        smu[O_W2T + i] = v;
    }
    for (int i = tid; i < DIRD * 64; i += 128) sm[O_W0D + i] = W0[i];
    if (tid < 64) { sm[O_B0 + tid] = b0[tid]; sm[O_B1 + tid] = b1[tid]; }
    if (tid < 8)  sm[O_B2 + tid] = (tid < 3) ? b2[tid] : 0.0f;
    for (int j = 9; j < 16; j++) smu[O_ACTG + agix(tid, j)] = 0;
    __syncthreads();

    const int gstride = gridDim.x;
    int row = blockIdx.x;

    // ---------- pipeline prologue: prefetch first row ----------
    float4 f4[6];
    float  dpre[DIRD];
    {
        const int2* xp2 = (const int2*)(x + ((size_t)row * BN + tid) * LVL);
        int2 xv0 = __ldg(xp2), xv1 = __ldg(xp2 + 1), xv2 = __ldg(xp2 + 2);
        if (tid < 64) {
            const float* dd = dvec + (size_t)row * DIRD;
            #pragma unroll
            for (int i = 0; i < DIRD; i++) dpre[i] = __ldg(dd + i);
        }
        f4[0] = __ldg(gw + xv0.x); f4[1] = __ldg(gw + xv0.y);
        f4[2] = __ldg(gw + xv1.x); f4[3] = __ldg(gw + xv1.y);
        f4[4] = __ldg(gw + xv2.x); f4[5] = __ldg(gw + xv2.y);
    }

    while (row < B) {
        const int nrow = row + gstride;
        const bool pn = nrow < B;

        // ============ phase 1: consume prefetched data ============
        if (tid < 64) {
            float acc = sm[O_B0 + tid];
            #pragma unroll
            for (int i = 0; i < DIRD; i++)
                acc = fmaf(dpre[i], sm[O_W0D + i * 64 + tid], acc);
            sm[O_BASE + tid] = acc;
        }
        float sg = 1.0f;
        float geo[GEO];
        #pragma unroll
        for (int l = 0; l < LVL; l++) {
            float4 f = f4[l];
            sg *= fminf(fmaxf(f.x, 0.0f), 1.0f);
            geo[3 * l] = f.y; geo[3 * l + 1] = f.z; geo[3 * l + 2] = f.w;
        }
        sg += 1e-4f;
        sm[O_SIG + tid] = sg;
        #pragma unroll
        for (int j = 0; j < 9; j++)
            smu[O_ACTG + agix(tid, j)] = pkbf(geo[2 * j], geo[2 * j + 1]);

        float m = sg;
        #pragma unroll
        for (int o = 16; o; o >>= 1) m = fmaxf(m, __shfl_xor_sync(0xffffffffu, m, o));
        if (lane == 0) sm[O_MAX + warp] = m;
        __syncthreads();   // (A)
        m = fmaxf(fmaxf(sm[O_MAX + 0], sm[O_MAX + 1]), fmaxf(sm[O_MAX + 2], sm[O_MAX + 3]));

        float sigma = sg / m;
        outSigma[(size_t)row * BN + tid] = sigma;
        float tb = tid ? 1.0f - sm[O_SIG + tid - 1] / m : 1.0f;
        float cw = tb * sigma;

        // ---- prefetch stage 1: next row's x indices + d vector ----
        int2 xv0, xv1, xv2;
        if (pn) {
            const int2* xp2 = (const int2*)(x + ((size_t)nrow * BN + tid) * LVL);
            xv0 = __ldg(xp2); xv1 = __ldg(xp2 + 1); xv2 = __ldg(xp2 + 2);
            if (tid < 64) {
                const float* dd = dvec + (size_t)nrow * DIRD;
                #pragma unroll
                for (int i = 0; i < DIRD; i++) dpre[i] = __ldg(dd + i);
            }
        }

        const int r0 = warp * 32 + grp;
        const int r1 = r0 + 16;

        // ============ layer 0 ============
        {
            u32 A[2][2][4];
            const u32* AG = smu + O_ACTG;
            #pragma unroll
            for (int mt = 0; mt < 2; mt++) {
                int rA = r0 + mt * 16, rB = rA + 8;
                #pragma unroll
                for (int k = 0; k < 2; k++) {
                    A[mt][k][0] = AG[agix(rA, k * 8 + tig)];
                    A[mt][k][1] = AG[agix(rB, k * 8 + tig)];
                    A[mt][k][2] = AG[agix(rA, k * 8 + 4 + tig)];
                    A[mt][k][3] = AG[agix(rB, k * 8 + 4 + tig)];
                }
            }
            const u32* WT = smu + O_W0GT;
            u32* AH = smu + O_ACTH;
            #pragma unroll
            for (int n = 0; n < 8; n++) {
                float bv0 = sm[O_BASE + n * 8 + 2 * tig];
                float bv1 = sm[O_BASE + n * 8 + 2 * tig + 1];
                float C0[4] = {bv0, bv1, bv0, bv1};
                float C1[4] = {bv0, bv1, bv0, bv1};
                #pragma unroll
                for (int k = 0; k < 2; k++) {
                    u32 bb0 = WT[(n * 8 + grp) * SW0G + k * 8 + tig];
                    u32 bb1 = WT[(n * 8 + grp) * SW0G + k * 8 + 4 + tig];
                    mma16(C0, A[0][k], bb0, bb1);
                    mma16(C1, A[1][k], bb0, bb1);
                }
                AH[r0 * SAH + n * 4 + tig]        = pkbf(fmaxf(C0[0], 0.f), fmaxf(C0[1], 0.f));
                AH[(r0 + 8) * SAH + n * 4 + tig]  = pkbf(fmaxf(C0[2], 0.f), fmaxf(C0[3], 0.f));
                AH[r1 * SAH + n * 4 + tig]        = pkbf(fmaxf(C1[0], 0.f), fmaxf(C1[1], 0.f));
                AH[(r1 + 8) * SAH + n * 4 + tig]  = pkbf(fmaxf(C1[2], 0.f), fmaxf(C1[3], 0.f));
            }
        }
        __syncwarp();

        // ---- prefetch stage 2: dependent grid gathers (x has arrived) ----
        if (pn) {
            f4[0] = __ldg(gw + xv0.x); f4[1] = __ldg(gw + xv0.y);
            f4[2] = __ldg(gw + xv1.x); f4[3] = __ldg(gw + xv1.y);
            f4[4] = __ldg(gw + xv2.x); f4[5] = __ldg(gw + xv2.y);
        }

        // ============ layer 1 (in-place) ============
        {
            u32 A[2][4][4];
            const u32* AH = smu + O_ACTH;
            #pragma unroll
            for (int mt = 0; mt < 2; mt++) {
                int rA = r0 + mt * 16, rB = rA + 8;
                #pragma unroll
                for (int k = 0; k < 4; k++) {
                    A[mt][k][0] = AH[rA * SAH + k * 8 + tig];
                    A[mt][k][1] = AH[rB * SAH + k * 8 + tig];
                    A[mt][k][2] = AH[rA * SAH + k * 8 + 4 + tig];
                    A[mt][k][3] = AH[rB * SAH + k * 8 + 4 + tig];
                }
            }
            __syncwarp();
            const u32* WT = smu + O_W1T;
            u32* AHw = smu + O_ACTH;
            #pragma unroll
            for (int n = 0; n < 8; n++) {
                float bv0 = sm[O_B1 + n * 8 + 2 * tig];
                float bv1 = sm[O_B1 + n * 8 + 2 * tig + 1];
                float C0[4] = {bv0, bv1, bv0, bv1};
                float C1[4] = {bv0, bv1, bv0, bv1};
                #pragma unroll
                for (int k = 0; k < 4; k++) {
                    u32 bb0 = WT[(n * 8 + grp) * SW1 + k * 8 + tig];
                    u32 bb1 = WT[(n * 8 + grp) * SW1 + k * 8 + 4 + tig];
                    mma16(C0, A[0][k], bb0, bb1);
                    mma16(C1, A[1][k], bb0, bb1);
                }
                AHw[r0 * SAH + n * 4 + tig]       = pkbf(fmaxf(C0[0], 0.f), fmaxf(C0[1], 0.f));
                AHw[(r0 + 8) * SAH + n * 4 + tig] = pkbf(fmaxf(C0[2], 0.f), fmaxf(C0[3], 0.f));
                AHw[r1 * SAH + n * 4 + tig]       = pkbf(fmaxf(C1[0], 0.f), fmaxf(C1[1], 0.f));
                AHw[(r1 + 8) * SAH + n * 4 + tig] = pkbf(fmaxf(C1[2], 0.f), fmaxf(C1[3], 0.f));
            }
        }
        __syncwarp();

        // ============ layer 2 ============
        {
            u32 A[2][4][4];
            const u32* AH = smu + O_ACTH;
            #pragma unroll
            for (int mt = 0; mt < 2; mt++) {
                int rA = r0 + mt * 16, rB = rA + 8;
                #pragma unroll
                for (int k = 0; k < 4; k++) {
                    A[mt][k][0] = AH[rA * SAH + k * 8 + tig];
                    A[mt][k][1] = AH[rB * SAH + k * 8 + tig];
                    A[mt][k][2] = AH[rA * SAH + k * 8 + 4 + tig];
                    A[mt][k][3] = AH[rB * SAH + k * 8 + 4 + tig];
                }
            }
            const u32* WT = smu + O_W2T;
            float bv0 = sm[O_B2 + 2 * tig];
            float bv1 = sm[O_B2 + 2 * tig + 1];
            float C0[4] = {bv0, bv1, bv0, bv1};
            float C1[4] = {bv0, bv1, bv0, bv1};
            #pragma unroll
            for (int k = 0; k < 4; k++) {
                u32 bb0 = WT[grp * SW2 + k * 8 + tig];
                u32 bb1 = WT[grp * SW2 + k * 8 + 4 + tig];
                mma16(C0, A[0][k], bb0, bb1);
                mma16(C1, A[1][k], bb0, bb1);
            }
            if (2 * tig < 3) {
                sm[O_COLB + r0 * SCB + 2 * tig]        = C0[0];
                sm[O_COLB + (r0 + 8) * SCB + 2 * tig]  = C0[2];
                sm[O_COLB + r1 * SCB + 2 * tig]        = C1[0];
                sm[O_COLB + (r1 + 8) * SCB + 2 * tig]  = C1[2];
            }
            if (2 * tig + 1 < 3) {
                sm[O_COLB + r0 * SCB + 2 * tig + 1]       = C0[1];
                sm[O_COLB + (r0 + 8) * SCB + 2 * tig + 1] = C0[3];
                sm[O_COLB + r1 * SCB + 2 * tig + 1]       = C1[1];
                sm[O_COLB + (r1 + 8) * SCB + 2 * tig + 1] = C1[3];
            }
        }
        __syncwarp();

        // ============ phase 3 ============
        float l0 = sm[O_COLB + tid * SCB + 0];
        float l1 = sm[O_COLB + tid * SCB + 1];
        float l2 = sm[O_COLB + tid * SCB + 2];
        float c0 = 1.0f / (1.0f + expf(-l0));
        float c1 = 1.0f / (1.0f + expf(-l1));
        float c2 = 1.0f / (1.0f + expf(-l2));
        float rr = cw * c0, gg = cw * c1, bb = cw * c2;
        #pragma unroll
        for (int o = 16; o; o >>= 1) {
            rr += __shfl_xor_sync(0xffffffffu, rr, o);
            gg += __shfl_xor_sync(0xffffffffu, gg, o);
            bb += __shfl_xor_sync(0xffffffffu, bb, o);
        }
        if (lane == 0) {
            sm[O_COL + warp * 3 + 0] = rr;
            sm[O_COL + warp * 3 + 1] = gg;
            sm[O_COL + warp * 3 + 2] = bb;
        }
        __syncthreads();   // (C)
        if (tid < 3) {
            outColor[(size_t)row * 3 + tid] =
                sm[O_COL + tid] + sm[O_COL + 3 + tid] +
                sm[O_COL + 6 + tid] + sm[O_COL + 9 + tid];
        }
        row = nrow;
    }
}

extern "C" void kernel_launch(void* const* d_in, const int* in_sizes, int n_in,
                              void* d_out, int out_size)
{
    const int*    x  = (const int*)d_in[0];
    const float*  dv = (const float*)d_in[1];
    const float4* gw = (const float4*)d_in[2];
    const float*  W0 = (const float*)d_in[3];
    const float*  b0 = (const float*)d_in[4];
    const float*  W1 = (const float*)d_in[5];
    const float*  b1 = (const float*)d_in[6];
    const float*  W2 = (const float*)d_in[7];
    const float*  b2 = (const float*)d_in[8];

    const int B = in_sizes[0] / (BN * LVL);   // 16384
    float* outSigma = (float*)d_out;
    float* outColor = (float*)d_out + (size_t)B * BN;

    cudaFuncSetAttribute(surf_pipe,
                         cudaFuncAttributeMaxDynamicSharedMemorySize, SMEM_BYTES);

    int grid = B < 444 ? B : 444;   // 3 blocks/SM persistent
    surf_pipe<<<grid, 128, SMEM_BYTES>>>(x, dv, gw, W0, b0, W1, b1, W2, b2,
                                         outSigma, outColor, B);
}

// round 7
// speedup vs baseline: 4.9640x; 1.1426x over previous
#include <cuda_runtime.h>
#include <cuda_bf16.h>
#include <math.h>

// SurfNetwork v6: register-resident MLP. C-fragment of layer k IS the A-fragment
// of layer k+1 (relu+bf16x2 pack in registers) -> no activation SMEM round-trips.
// Retains v5's software-pipelined gather. 3 blocks/SM, smem ~36KB.

#define BN   128
#define LVL  6
#define DIRD 16
#define GEO  18

#define SW0G 20
#define SW1  36
#define SW2  36
#define SAG  20
#define SCB  9

typedef unsigned int u32;

#define O_W0GT 0        // 64*20
#define O_W1T  1280     // 64*36
#define O_W2T  3584     // 8*36
#define O_W0D  3872     // 16*64 fp32
#define O_B0   4896
#define O_B1   4960
#define O_B2   5024
#define O_BASE 5032
#define O_SIG  5096
#define O_MAX  5224
#define O_COL  5228
#define O_ACTG 5240     // 128*20
#define O_COLB 7800     // 128*9 fp32
#define SMEM_WORDS 8952
#define SMEM_BYTES (SMEM_WORDS * 4)   // 35808

__device__ __forceinline__ u32 pkbf(float lo, float hi) {
    u32 r; asm("cvt.rn.bf16x2.f32 %0, %1, %2;" : "=r"(r) : "f"(hi), "f"(lo));
    return r;
}
__device__ __forceinline__ u32 pkrelu(float lo, float hi) {
    return pkbf(fmaxf(lo, 0.0f), fmaxf(hi, 0.0f));
}
__device__ __forceinline__ void mma16(float* c, const u32* a, u32 b0, u32 b1) {
    asm volatile(
        "mma.sync.aligned.m16n8k16.row.col.f32.bf16.bf16.f32 "
        "{%0,%1,%2,%3},{%4,%5,%6,%7},{%8,%9},{%0,%1,%2,%3};"
        : "+f"(c[0]), "+f"(c[1]), "+f"(c[2]), "+f"(c[3])
        : "r"(a[0]), "r"(a[1]), "r"(a[2]), "r"(a[3]), "r"(b0), "r"(b1));
}
__device__ __forceinline__ int agix(int row, int j) {
    return row * SAG + (j ^ ((row >> 3) & 3));
}

__global__ void __launch_bounds__(128, 3)
surf_reg(const int* __restrict__ x,
         const float* __restrict__ dvec,
         const float4* __restrict__ gw,
         const float* __restrict__ W0, const float* __restrict__ b0,
         const float* __restrict__ W1, const float* __restrict__ b1,
         const float* __restrict__ W2, const float* __restrict__ b2,
         float* __restrict__ outSigma, float* __restrict__ outColor,
         int B)
{
    extern __shared__ float sm[];
    u32* smu = (u32*)sm;
    const int tid  = threadIdx.x;
    const int lane = tid & 31;
    const int warp = tid >> 5;
    const int grp  = lane >> 2;
    const int tig  = lane & 3;

    // ---------- stage weights (transposed, bf16x2) ----------
    for (int i = tid; i < 64 * SW0G; i += 128) {
        int n = i / SW0G, kk = i - n * SW0G;
        u32 v = 0;
        if (kk < 16) {
            int g0 = 2 * kk, g1 = 2 * kk + 1;
            float lo = (g0 < GEO) ? W0[(DIRD + g0) * 64 + n] : 0.0f;
            float hi = (g1 < GEO) ? W0[(DIRD + g1) * 64 + n] : 0.0f;
            v = pkbf(lo, hi);
        }
        smu[O_W0GT + i] = v;
    }
    for (int i = tid; i < 64 * SW1; i += 128) {
        int n = i / SW1, kk = i - n * SW1;
        u32 v = 0;
        if (kk < 32) v = pkbf(W1[(2 * kk) * 64 + n], W1[(2 * kk + 1) * 64 + n]);
        smu[O_W1T + i] = v;
    }
    for (int i = tid; i < 8 * SW2; i += 128) {
        int n = i / SW2, kk = i - n * SW2;
        u32 v = 0;
        if (kk < 32 && n < 3) v = pkbf(W2[(2 * kk) * 3 + n], W2[(2 * kk + 1) * 3 + n]);
        smu[O_W2T + i] = v;
    }
    for (int i = tid; i < DIRD * 64; i += 128) sm[O_W0D + i] = W0[i];
    if (tid < 64) { sm[O_B0 + tid] = b0[tid]; sm[O_B1 + tid] = b1[tid]; }
    if (tid < 8)  sm[O_B2 + tid] = (tid < 3) ? b2[tid] : 0.0f;
    for (int j = 9; j < 16; j++) smu[O_ACTG + agix(tid, j)] = 0;
    __syncthreads();

    const int gstride = gridDim.x;
    int row = blockIdx.x;

    // ---------- prologue prefetch ----------
    float4 f4[6];
    float  dpre[DIRD];
    {
        const int2* xp2 = (const int2*)(x + ((size_t)row * BN + tid) * LVL);
        int2 xv0 = __ldg(xp2), xv1 = __ldg(xp2 + 1), xv2 = __ldg(xp2 + 2);
        if (tid < 64) {
            const float* dd = dvec + (size_t)row * DIRD;
            #pragma unroll
            for (int i = 0; i < DIRD; i++) dpre[i] = __ldg(dd + i);
        }
        f4[0] = __ldg(gw + xv0.x); f4[1] = __ldg(gw + xv0.y);
        f4[2] = __ldg(gw + xv1.x); f4[3] = __ldg(gw + xv1.y);
        f4[4] = __ldg(gw + xv2.x); f4[5] = __ldg(gw + xv2.y);
    }

    while (row < B) {
        const int nrow = row + gstride;
        const bool pn = nrow < B;

        // ============ phase 1 ============
        if (tid < 64) {
            float acc = sm[O_B0 + tid];
            #pragma unroll
            for (int i = 0; i < DIRD; i++)
                acc = fmaf(dpre[i], sm[O_W0D + i * 64 + tid], acc);
            sm[O_BASE + tid] = acc;
        }
        float sg = 1.0f;
        float geo[GEO];
        #pragma unroll
        for (int l = 0; l < LVL; l++) {
            float4 f = f4[l];
            sg *= fminf(fmaxf(f.x, 0.0f), 1.0f);
            geo[3 * l] = f.y; geo[3 * l + 1] = f.z; geo[3 * l + 2] = f.w;
        }
        sg += 1e-4f;
        sm[O_SIG + tid] = sg;
        #pragma unroll
        for (int j = 0; j < 9; j++)
            smu[O_ACTG + agix(tid, j)] = pkbf(geo[2 * j], geo[2 * j + 1]);

        float m = sg;
        #pragma unroll
        for (int o = 16; o; o >>= 1) m = fmaxf(m, __shfl_xor_sync(0xffffffffu, m, o));
        if (lane == 0) sm[O_MAX + warp] = m;
        __syncthreads();   // (A)
        m = fmaxf(fmaxf(sm[O_MAX + 0], sm[O_MAX + 1]), fmaxf(sm[O_MAX + 2], sm[O_MAX + 3]));

        float sigma = sg / m;
        outSigma[(size_t)row * BN + tid] = sigma;
        float tb = tid ? 1.0f - sm[O_SIG + tid - 1] / m : 1.0f;
        float cw = tb * sigma;

        // ---- prefetch stage 1 ----
        int2 xv0, xv1, xv2;
        if (pn) {
            const int2* xp2 = (const int2*)(x + ((size_t)nrow * BN + tid) * LVL);
            xv0 = __ldg(xp2); xv1 = __ldg(xp2 + 1); xv2 = __ldg(xp2 + 2);
            if (tid < 64) {
                const float* dd = dvec + (size_t)nrow * DIRD;
                #pragma unroll
                for (int i = 0; i < DIRD; i++) dpre[i] = __ldg(dd + i);
            }
        }

        const int r0 = warp * 32 + grp;

        // ============ layer 0 -> A1 registers ============
        u32 A1[2][4][4];
        {
            u32 Ag[2][2][4];
            const u32* AG = smu + O_ACTG;
            #pragma unroll
            for (int mt = 0; mt < 2; mt++) {
                int rA = r0 + mt * 16, rB = rA + 8;
                #pragma unroll
                for (int k = 0; k < 2; k++) {
                    Ag[mt][k][0] = AG[agix(rA, k * 8 + tig)];
                    Ag[mt][k][1] = AG[agix(rB, k * 8 + tig)];
                    Ag[mt][k][2] = AG[agix(rA, k * 8 + 4 + tig)];
                    Ag[mt][k][3] = AG[agix(rB, k * 8 + 4 + tig)];
                }
            }
            const u32* WT = smu + O_W0GT;
            #pragma unroll
            for (int kg = 0; kg < 4; kg++) {       // output n-pair (2kg, 2kg+1)
                float Ca[2][4], Cb[2][4];
                #pragma unroll
                for (int mt = 0; mt < 2; mt++) {
                    float v0 = sm[O_BASE + (2 * kg) * 8 + 2 * tig];
                    float v1 = sm[O_BASE + (2 * kg) * 8 + 2 * tig + 1];
                    Ca[mt][0] = v0; Ca[mt][1] = v1; Ca[mt][2] = v0; Ca[mt][3] = v1;
                    v0 = sm[O_BASE + (2 * kg + 1) * 8 + 2 * tig];
                    v1 = sm[O_BASE + (2 * kg + 1) * 8 + 2 * tig + 1];
                    Cb[mt][0] = v0; Cb[mt][1] = v1; Cb[mt][2] = v0; Cb[mt][3] = v1;
                }
                #pragma unroll
                for (int k = 0; k < 2; k++) {
                    u32 ba0 = WT[((2 * kg) * 8 + grp) * SW0G + k * 8 + tig];
                    u32 ba1 = WT[((2 * kg) * 8 + grp) * SW0G + k * 8 + 4 + tig];
                    u32 bb0 = WT[((2 * kg + 1) * 8 + grp) * SW0G + k * 8 + tig];
                    u32 bb1 = WT[((2 * kg + 1) * 8 + grp) * SW0G + k * 8 + 4 + tig];
                    #pragma unroll
                    for (int mt = 0; mt < 2; mt++) {
                        mma16(Ca[mt], Ag[mt][k], ba0, ba1);
                        mma16(Cb[mt], Ag[mt][k], bb0, bb1);
                    }
                }
                #pragma unroll
                for (int mt = 0; mt < 2; mt++) {
                    A1[mt][kg][0] = pkrelu(Ca[mt][0], Ca[mt][1]);
                    A1[mt][kg][1] = pkrelu(Ca[mt][2], Ca[mt][3]);
                    A1[mt][kg][2] = pkrelu(Cb[mt][0], Cb[mt][1]);
                    A1[mt][kg][3] = pkrelu(Cb[mt][2], Cb[mt][3]);
                }
            }
        }

        // ---- prefetch stage 2: dependent grid gathers ----
        if (pn) {
            f4[0] = __ldg(gw + xv0.x); f4[1] = __ldg(gw + xv0.y);
            f4[2] = __ldg(gw + xv1.x); f4[3] = __ldg(gw + xv1.y);
            f4[4] = __ldg(gw + xv2.x); f4[5] = __ldg(gw + xv2.y);
        }

        // ============ layer 1 -> A2 registers ============
        u32 A2[2][4][4];
        {
            const u32* WT = smu + O_W1T;
            #pragma unroll
            for (int kg = 0; kg < 4; kg++) {       // output n-pair
                float Ca[2][4], Cb[2][4];
                #pragma unroll
                for (int mt = 0; mt < 2; mt++) {
                    float v0 = sm[O_B1 + (2 * kg) * 8 + 2 * tig];
                    float v1 = sm[O_B1 + (2 * kg) * 8 + 2 * tig + 1];
                    Ca[mt][0] = v0; Ca[mt][1] = v1; Ca[mt][2] = v0; Ca[mt][3] = v1;
                    v0 = sm[O_B1 + (2 * kg + 1) * 8 + 2 * tig];
                    v1 = sm[O_B1 + (2 * kg + 1) * 8 + 2 * tig + 1];
                    Cb[mt][0] = v0; Cb[mt][1] = v1; Cb[mt][2] = v0; Cb[mt][3] = v1;
                }
                #pragma unroll
                for (int k = 0; k < 4; k++) {
                    u32 ba0 = WT[((2 * kg) * 8 + grp) * SW1 + k * 8 + tig];
                    u32 ba1 = WT[((2 * kg) * 8 + grp) * SW1 + k * 8 + 4 + tig];
                    u32 bb0 = WT[((2 * kg + 1) * 8 + grp) * SW1 + k * 8 + tig];
                    u32 bb1 = WT[((2 * kg + 1) * 8 + grp) * SW1 + k * 8 + 4 + tig];
                    #pragma unroll
                    for (int mt = 0; mt < 2; mt++) {
                        mma16(Ca[mt], A1[mt][k], ba0, ba1);
                        mma16(Cb[mt], A1[mt][k], bb0, bb1);
                    }
                }
                #pragma unroll
                for (int mt = 0; mt < 2; mt++) {
                    A2[mt][kg][0] = pkrelu(Ca[mt][0], Ca[mt][1]);
                    A2[mt][kg][1] = pkrelu(Ca[mt][2], Ca[mt][3]);
                    A2[mt][kg][2] = pkrelu(Cb[mt][0], Cb[mt][1]);
                    A2[mt][kg][3] = pkrelu(Cb[mt][2], Cb[mt][3]);
                }
            }
        }

        // ============ layer 2 -> logits ============
        {
            const u32* WT = smu + O_W2T;
            float bv0 = sm[O_B2 + 2 * tig];
            float bv1 = sm[O_B2 + 2 * tig + 1];
            float C0[4] = {bv0, bv1, bv0, bv1};
            float C1[4] = {bv0, bv1, bv0, bv1};
            #pragma unroll
            for (int k = 0; k < 4; k++) {
                u32 bb0 = WT[grp * SW2 + k * 8 + tig];
                u32 bb1 = WT[grp * SW2 + k * 8 + 4 + tig];
                mma16(C0, A2[0][k], bb0, bb1);
                mma16(C1, A2[1][k], bb0, bb1);
            }
            const int r1 = r0 + 16;
            if (2 * tig < 3) {
                sm[O_COLB + r0 * SCB + 2 * tig]        = C0[0];
                sm[O_COLB + (r0 + 8) * SCB + 2 * tig]  = C0[2];
                sm[O_COLB + r1 * SCB + 2 * tig]        = C1[0];
                sm[O_COLB + (r1 + 8) * SCB + 2 * tig]  = C1[2];
            }
            if (2 * tig + 1 < 3) {
                sm[O_COLB + r0 * SCB + 2 * tig + 1]       = C0[1];
                sm[O_COLB + (r0 + 8) * SCB + 2 * tig + 1] = C0[3];
                sm[O_COLB + r1 * SCB + 2 * tig + 1]       = C1[1];
                sm[O_COLB + (r1 + 8) * SCB + 2 * tig + 1] = C1[3];
            }
        }
        __syncwarp();

        // ============ phase 3 ============
        float l0 = sm[O_COLB + tid * SCB + 0];
        float l1 = sm[O_COLB + tid * SCB + 1];
        float l2 = sm[O_COLB + tid * SCB + 2];
        float c0 = 1.0f / (1.0f + expf(-l0));
        float c1 = 1.0f / (1.0f + expf(-l1));
        float c2 = 1.0f / (1.0f + expf(-l2));
        float rr = cw * c0, gg = cw * c1, bb = cw * c2;
        #pragma unroll
        for (int o = 16; o; o >>= 1) {
            rr += __shfl_xor_sync(0xffffffffu, rr, o);
            gg += __shfl_xor_sync(0xffffffffu, gg, o);
            bb += __shfl_xor_sync(0xffffffffu, bb, o);
        }
        if (lane == 0) {
            sm[O_COL + warp * 3 + 0] = rr;
            sm[O_COL + warp * 3 + 1] = gg;
            sm[O_COL + warp * 3 + 2] = bb;
        }
        __syncthreads();   // (C)
        if (tid < 3) {
            outColor[(size_t)row * 3 + tid] =
                sm[O_COL + tid] + sm[O_COL + 3 + tid] +
                sm[O_COL + 6 + tid] + sm[O_COL + 9 + tid];
        }
        row = nrow;
    }
}

extern "C" void kernel_launch(void* const* d_in, const int* in_sizes, int n_in,
                              void* d_out, int out_size)
{
    const int*    x  = (const int*)d_in[0];
    const float*  dv = (const float*)d_in[1];
    const float4* gw = (const float4*)d_in[2];
    const float*  W0 = (const float*)d_in[3];
    const float*  b0 = (const float*)d_in[4];
    const float*  W1 = (const float*)d_in[5];
    const float*  b1 = (const float*)d_in[6];
    const float*  W2 = (const float*)d_in[7];
    const float*  b2 = (const float*)d_in[8];

    const int B = in_sizes[0] / (BN * LVL);   // 16384
    float* outSigma = (float*)d_out;
    float* outColor = (float*)d_out + (size_t)B * BN;

    cudaFuncSetAttribute(surf_reg,
                         cudaFuncAttributeMaxDynamicSharedMemorySize, SMEM_BYTES);

    int grid = B < 444 ? B : 444;   // 3 blocks/SM persistent
    surf_reg<<<grid, 128, SMEM_BYTES>>>(x, dv, gw, W0, b0, W1, b1, W2, b2,
                                        outSigma, outColor, B);
}